// round 3
// baseline (speedup 1.0000x reference)
#include <cuda_runtime.h>
#include <math.h>
#include <stdint.h>

// Problem constants
#define NTOK 2048
#define DIM  1024
#define FF   4096
#define FSH  2048
#define NE   8
#define TOPK 2
#define NSLOT (NTOK*TOPK)

// Tiling: BM=128, BN=64, BK=32; 256 thr = 8 warps, each warp computes 16(M)x64(N)
#define BM 128
#define BN 64
#define BK 32
#define PITCH_A 36
#define PITCH_B 72

// ---- scratch ----
__device__ float g_act[(size_t)NSLOT * FF];
__device__ float g_eo[(size_t)NSLOT * DIM];
__device__ float g_hs[(size_t)NTOK * FSH];
__device__ float g_topw[NTOK * TOPK];
__device__ int   g_topi[NTOK * TOPK];
__device__ int   g_slot_tok[NSLOT];
__device__ float g_slot_w[NSLOT];
__device__ int   g_slot_dst[NSLOT];
__device__ int   g_cnt[NE];
__device__ int   g_off[NE + 1];

// ---------------------------------------------------------------------------
__device__ __forceinline__ uint32_t f2tf32(float x) {
    uint32_t r;
    asm("cvt.rna.tf32.f32 %0, %1;" : "=r"(r) : "f"(x));
    return r;
}

__device__ __forceinline__ void mma_tf32(float& c0, float& c1, float& c2, float& c3,
                                         uint32_t a0, uint32_t a1, uint32_t a2, uint32_t a3,
                                         uint32_t b0, uint32_t b1)
{
    asm volatile(
        "mma.sync.aligned.m16n8k8.row.col.f32.tf32.tf32.f32 "
        "{%0,%1,%2,%3},{%4,%5,%6,%7},{%8,%9},{%0,%1,%2,%3};"
        : "+f"(c0), "+f"(c1), "+f"(c2), "+f"(c3)
        : "r"(a0), "r"(a1), "r"(a2), "r"(a3), "r"(b0), "r"(b1));
}

// Store a 16-float strip of A into the permuted layout.
// As[m][pos(k)], pos(k) = (k&3)*8 + (k>>2), row pitch PITCH_A.
__device__ __forceinline__ void sts_A_perm(float* As, int a_row, int a_k0, const float4* avr)
{
    float* rowp = As + a_row * PITCH_A;
#pragma unroll
    for (int l = 0; l < 4; l++) {
        float v0 = avr[l].x, v1 = avr[l].y, v2 = avr[l].z, v3 = avr[l].w;
        int kb = a_k0 + l * 4;
        rowp[((kb + 0) & 3) * 8 + ((kb + 0) >> 2)] = v0;
        rowp[((kb + 1) & 3) * 8 + ((kb + 1) >> 2)] = v1;
        rowp[((kb + 2) & 3) * 8 + ((kb + 2) >> 2)] = v2;
        rowp[((kb + 3) & 3) * 8 + ((kb + 3) >> 2)] = v3;
    }
}

// Load + convert this warp's A fragments for the whole BK=32 chunk.
// u[h][v][c]: h = row half (q / q+8), v = lo/hi float4 (j 0-3 / 4-7), c = comp.
struct AFrag { uint32_t u[2][2][4]; };

__device__ __forceinline__ void load_afrag(AFrag& f, const float* As, int row0, int r)
{
#pragma unroll
    for (int h = 0; h < 2; h++) {
        const float* p = As + (size_t)(row0 + h * 8) * PITCH_A + r * 8;
        float4 lo = *(const float4*)p;
        float4 hi = *(const float4*)(p + 4);
        f.u[h][0][0] = f2tf32(lo.x); f.u[h][0][1] = f2tf32(lo.y);
        f.u[h][0][2] = f2tf32(lo.z); f.u[h][0][3] = f2tf32(lo.w);
        f.u[h][1][0] = f2tf32(hi.x); f.u[h][1][1] = f2tf32(hi.y);
        f.u[h][1][2] = f2tf32(hi.z); f.u[h][1][3] = f2tf32(hi.w);
    }
}

// ---------------------------------------------------------------------------
// Router + compaction (unchanged)
// ---------------------------------------------------------------------------
__global__ void router_kernel(const float* __restrict__ x,
                              const float* __restrict__ gate_w)
{
    const int n = blockIdx.x;
    const int tid = threadIdx.x;
    __shared__ float sred[NE][128];

    float acc[NE];
#pragma unroll
    for (int e = 0; e < NE; e++) acc[e] = 0.f;

    const float* xr = x + (size_t)n * DIM;
    for (int d = tid; d < DIM; d += 128) {
        float xv = xr[d];
#pragma unroll
        for (int e = 0; e < NE; e++)
            acc[e] = fmaf(xv, gate_w[e * DIM + d], acc[e]);
    }
#pragma unroll
    for (int e = 0; e < NE; e++) sred[e][tid] = acc[e];
    __syncthreads();

    if (tid < NE) {
        float s = 0.f;
        for (int i = 0; i < 128; i++) s += sred[tid][i];
        sred[tid][0] = s;
    }
    __syncthreads();

    if (tid == 0) {
        float lg[NE];
#pragma unroll
        for (int e = 0; e < NE; e++) lg[e] = sred[e][0];
        float mx = lg[0];
#pragma unroll
        for (int e = 1; e < NE; e++) mx = fmaxf(mx, lg[e]);
        float se = 0.f, p[NE];
#pragma unroll
        for (int e = 0; e < NE; e++) { p[e] = expf(lg[e] - mx); se += p[e]; }
        float inv = 1.f / se;
#pragma unroll
        for (int e = 0; e < NE; e++) p[e] *= inv;

        int i1 = 0; float v1 = p[0];
#pragma unroll
        for (int e = 1; e < NE; e++) if (p[e] > v1) { v1 = p[e]; i1 = e; }
        int i2 = -1; float v2 = -1.f;
#pragma unroll
        for (int e = 0; e < NE; e++) if (e != i1 && p[e] > v2) { v2 = p[e]; i2 = e; }

        g_topi[n * 2 + 0] = i1;  g_topw[n * 2 + 0] = v1;
        g_topi[n * 2 + 1] = i2;  g_topw[n * 2 + 1] = v2;
        atomicAdd(&g_cnt[i1], 1);
        atomicAdd(&g_cnt[i2], 1);
    }
}

__global__ void zero_cnt_kernel()
{
    if (threadIdx.x < NE) g_cnt[threadIdx.x] = 0;
}

__global__ void scan_kernel()
{
    if (threadIdx.x == 0) {
        int r = 0;
        for (int e = 0; e < NE; e++) { g_off[e] = r; r += g_cnt[e]; g_cnt[e] = 0; }
        g_off[NE] = r;
    }
}

__global__ void fill_kernel()
{
    int n = blockIdx.x * blockDim.x + threadIdx.x;
    if (n >= NTOK) return;
#pragma unroll
    for (int k = 0; k < TOPK; k++) {
        int e = g_topi[n * 2 + k];
        int pos = atomicAdd(&g_cnt[e], 1);
        int slot = g_off[e] + pos;
        g_slot_tok[slot] = n;
        g_slot_w[slot]   = g_topw[n * 2 + k];
        g_slot_dst[slot] = n * 2 + k;
    }
}

// ---------------------------------------------------------------------------
// Routed gate+up GEMM (pipelined, vectorized A) + SwiGLU + weight
// ---------------------------------------------------------------------------
__global__ __launch_bounds__(256)
void gemm_gateup_routed(const float* __restrict__ x,
                        const float* __restrict__ gate_k,
                        const float* __restrict__ up_k)
{
    const int e = blockIdx.z;
    const int cnt = g_cnt[e];
    const int rowbase = blockIdx.y * BM;
    if (rowbase >= cnt) return;
    const int off = g_off[e];
    const int n0 = blockIdx.x * BN;
    const float* __restrict__ Bg = gate_k + (size_t)e * DIM * FF;
    const float* __restrict__ Bu = up_k   + (size_t)e * DIM * FF;

    __shared__ float As[BM * PITCH_A];
    __shared__ float Bgs[BK * PITCH_B];
    __shared__ float Bus[BK * PITCH_B];

    const int t = threadIdx.x;
    const int wid = t >> 5, lane = t & 31;
    const int q = lane >> 2, r = lane & 3;
    const int wrow = wid * 16;

    const int a_row = t >> 1, a_k0 = (t & 1) * 16;
    int m_g = rowbase + a_row;
    if (m_g >= cnt) m_g = cnt - 1;
    const float* a_src = x + (size_t)g_slot_tok[off + m_g] * DIM;

    const int b_row = t >> 3, b_col = (t & 7) * 8;
    const float* bg_src = Bg + (size_t)b_row * FF + n0 + b_col;
    const float* bu_src = Bu + (size_t)b_row * FF + n0 + b_col;

    float accg[8][4], accu[8][4];
#pragma unroll
    for (int nt = 0; nt < 8; nt++)
#pragma unroll
        for (int c = 0; c < 4; c++) { accg[nt][c] = 0.f; accu[nt][c] = 0.f; }

    float4 avr[4], bgr[2], bur[2];
#pragma unroll
    for (int l = 0; l < 4; l++) avr[l] = *(const float4*)(a_src + a_k0 + l * 4);
    bgr[0] = *(const float4*)(bg_src);
    bgr[1] = *(const float4*)(bg_src + 4);
    bur[0] = *(const float4*)(bu_src);
    bur[1] = *(const float4*)(bu_src + 4);

#pragma unroll 1
    for (int k0 = 0; k0 < DIM; k0 += BK) {
        __syncthreads();
        sts_A_perm(As, a_row, a_k0, avr);
        *(float4*)&Bgs[b_row * PITCH_B + b_col]     = bgr[0];
        *(float4*)&Bgs[b_row * PITCH_B + b_col + 4] = bgr[1];
        *(float4*)&Bus[b_row * PITCH_B + b_col]     = bur[0];
        *(float4*)&Bus[b_row * PITCH_B + b_col + 4] = bur[1];
        __syncthreads();

        if (k0 + BK < DIM) {
#pragma unroll
            for (int l = 0; l < 4; l++)
                avr[l] = *(const float4*)(a_src + k0 + BK + a_k0 + l * 4);
            bgr[0] = *(const float4*)(bg_src + (size_t)(k0 + BK) * FF);
            bgr[1] = *(const float4*)(bg_src + (size_t)(k0 + BK) * FF + 4);
            bur[0] = *(const float4*)(bu_src + (size_t)(k0 + BK) * FF);
            bur[1] = *(const float4*)(bu_src + (size_t)(k0 + BK) * FF + 4);
        }

        AFrag af;
        load_afrag(af, As, wrow + q, r);
#pragma unroll
        for (int s = 0; s < 4; s++) {
            const int v = s >> 1, c0 = (s & 1) * 2;
            uint32_t a0 = af.u[0][v][c0],     a1 = af.u[1][v][c0];
            uint32_t a2 = af.u[0][v][c0 + 1], a3 = af.u[1][v][c0 + 1];
            const float* brow0g = Bgs + (size_t)(s * 8 + r) * PITCH_B;
            const float* brow1g = Bgs + (size_t)(s * 8 + 4 + r) * PITCH_B;
            const float* brow0u = Bus + (size_t)(s * 8 + r) * PITCH_B;
            const float* brow1u = Bus + (size_t)(s * 8 + 4 + r) * PITCH_B;
#pragma unroll
            for (int nt = 0; nt < 8; nt++) {
                int nc = nt * 8 + q;
                uint32_t bg0 = f2tf32(brow0g[nc]);
                uint32_t bg1 = f2tf32(brow1g[nc]);
                mma_tf32(accg[nt][0], accg[nt][1], accg[nt][2], accg[nt][3],
                         a0, a1, a2, a3, bg0, bg1);
                uint32_t bu0 = f2tf32(brow0u[nc]);
                uint32_t bu1 = f2tf32(brow1u[nc]);
                mma_tf32(accu[nt][0], accu[nt][1], accu[nt][2], accu[nt][3],
                         a0, a1, a2, a3, bu0, bu1);
            }
        }
    }

#pragma unroll
    for (int h = 0; h < 2; h++) {
        int m = rowbase + wrow + q + h * 8;
        if (m < cnt) {
            int slot = off + m;
            float w = g_slot_w[slot];
            float* dst = g_act + (size_t)slot * FF + n0;
#pragma unroll
            for (int nt = 0; nt < 8; nt++) {
                int cb = nt * 8 + 2 * r;
                float gv0 = accg[nt][h * 2 + 0], gv1 = accg[nt][h * 2 + 1];
                float uv0 = accu[nt][h * 2 + 0], uv1 = accu[nt][h * 2 + 1];
                dst[cb]     = w * (gv0 / (1.f + expf(-gv0))) * uv0;
                dst[cb + 1] = w * (gv1 / (1.f + expf(-gv1))) * uv1;
            }
        }
    }
}

// ---------------------------------------------------------------------------
// Routed down GEMM (pipelined, vectorized A)
// ---------------------------------------------------------------------------
__global__ __launch_bounds__(256)
void gemm_down_routed(const float* __restrict__ down_k)
{
    const int e = blockIdx.z;
    const int cnt = g_cnt[e];
    const int rowbase = blockIdx.y * BM;
    if (rowbase >= cnt) return;
    const int off = g_off[e];
    const int n0 = blockIdx.x * BN;
    const float* __restrict__ B = down_k + (size_t)e * FF * DIM;

    __shared__ float As[BM * PITCH_A];
    __shared__ float Bs[BK * PITCH_B];

    const int t = threadIdx.x;
    const int wid = t >> 5, lane = t & 31;
    const int q = lane >> 2, r = lane & 3;
    const int wrow = wid * 16;

    const int a_row = t >> 1, a_k0 = (t & 1) * 16;
    int m_g = rowbase + a_row;
    if (m_g >= cnt) m_g = cnt - 1;
    const float* a_src = g_act + (size_t)(off + m_g) * FF;

    const int b_row = t >> 3, b_col = (t & 7) * 8;
    const float* b_src = B + (size_t)b_row * DIM + n0 + b_col;

    float acc[8][4];
#pragma unroll
    for (int nt = 0; nt < 8; nt++)
#pragma unroll
        for (int c = 0; c < 4; c++) acc[nt][c] = 0.f;

    float4 avr[4], bvr[2];
#pragma unroll
    for (int l = 0; l < 4; l++) avr[l] = *(const float4*)(a_src + a_k0 + l * 4);
    bvr[0] = *(const float4*)(b_src);
    bvr[1] = *(const float4*)(b_src + 4);

#pragma unroll 1
    for (int k0 = 0; k0 < FF; k0 += BK) {
        __syncthreads();
        sts_A_perm(As, a_row, a_k0, avr);
        *(float4*)&Bs[b_row * PITCH_B + b_col]     = bvr[0];
        *(float4*)&Bs[b_row * PITCH_B + b_col + 4] = bvr[1];
        __syncthreads();

        if (k0 + BK < FF) {
#pragma unroll
            for (int l = 0; l < 4; l++)
                avr[l] = *(const float4*)(a_src + k0 + BK + a_k0 + l * 4);
            bvr[0] = *(const float4*)(b_src + (size_t)(k0 + BK) * DIM);
            bvr[1] = *(const float4*)(b_src + (size_t)(k0 + BK) * DIM + 4);
        }

        AFrag af;
        load_afrag(af, As, wrow + q, r);
#pragma unroll
        for (int s = 0; s < 4; s++) {
            const int v = s >> 1, c0 = (s & 1) * 2;
            uint32_t a0 = af.u[0][v][c0],     a1 = af.u[1][v][c0];
            uint32_t a2 = af.u[0][v][c0 + 1], a3 = af.u[1][v][c0 + 1];
            const float* brow0 = Bs + (size_t)(s * 8 + r) * PITCH_B;
            const float* brow1 = Bs + (size_t)(s * 8 + 4 + r) * PITCH_B;
#pragma unroll
            for (int nt = 0; nt < 8; nt++) {
                int nc = nt * 8 + q;
                uint32_t b0 = f2tf32(brow0[nc]);
                uint32_t b1 = f2tf32(brow1[nc]);
                mma_tf32(acc[nt][0], acc[nt][1], acc[nt][2], acc[nt][3],
                         a0, a1, a2, a3, b0, b1);
            }
        }
    }

#pragma unroll
    for (int h = 0; h < 2; h++) {
        int m = rowbase + wrow + q + h * 8;
        if (m < cnt) {
            int dst_row = g_slot_dst[off + m];
            float* dst = g_eo + (size_t)dst_row * DIM + n0;
#pragma unroll
            for (int nt = 0; nt < 8; nt++) {
                int cb = nt * 8 + 2 * r;
                dst[cb]     = acc[nt][h * 2 + 0];
                dst[cb + 1] = acc[nt][h * 2 + 1];
            }
        }
    }
}

// ---------------------------------------------------------------------------
// Shared expert gate+up + SwiGLU
// ---------------------------------------------------------------------------
__global__ __launch_bounds__(256)
void gemm_gateup_shared(const float* __restrict__ x,
                        const float* __restrict__ sh_gate,
                        const float* __restrict__ sh_up)
{
    const int rowbase = blockIdx.y * BM;
    const int n0 = blockIdx.x * BN;

    __shared__ float As[BM * PITCH_A];
    __shared__ float Bgs[BK * PITCH_B];
    __shared__ float Bus[BK * PITCH_B];

    const int t = threadIdx.x;
    const int wid = t >> 5, lane = t & 31;
    const int q = lane >> 2, r = lane & 3;
    const int wrow = wid * 16;

    const int a_row = t >> 1, a_k0 = (t & 1) * 16;
    const float* a_src = x + (size_t)(rowbase + a_row) * DIM;

    const int b_row = t >> 3, b_col = (t & 7) * 8;
    const float* bg_src = sh_gate + (size_t)b_row * FSH + n0 + b_col;
    const float* bu_src = sh_up   + (size_t)b_row * FSH + n0 + b_col;

    float accg[8][4], accu[8][4];
#pragma unroll
    for (int nt = 0; nt < 8; nt++)
#pragma unroll
        for (int c = 0; c < 4; c++) { accg[nt][c] = 0.f; accu[nt][c] = 0.f; }

    float4 avr[4], bgr[2], bur[2];
#pragma unroll
    for (int l = 0; l < 4; l++) avr[l] = *(const float4*)(a_src + a_k0 + l * 4);
    bgr[0] = *(const float4*)(bg_src);
    bgr[1] = *(const float4*)(bg_src + 4);
    bur[0] = *(const float4*)(bu_src);
    bur[1] = *(const float4*)(bu_src + 4);

#pragma unroll 1
    for (int k0 = 0; k0 < DIM; k0 += BK) {
        __syncthreads();
        sts_A_perm(As, a_row, a_k0, avr);
        *(float4*)&Bgs[b_row * PITCH_B + b_col]     = bgr[0];
        *(float4*)&Bgs[b_row * PITCH_B + b_col + 4] = bgr[1];
        *(float4*)&Bus[b_row * PITCH_B + b_col]     = bur[0];
        *(float4*)&Bus[b_row * PITCH_B + b_col + 4] = bur[1];
        __syncthreads();

        if (k0 + BK < DIM) {
#pragma unroll
            for (int l = 0; l < 4; l++)
                avr[l] = *(const float4*)(a_src + k0 + BK + a_k0 + l * 4);
            bgr[0] = *(const float4*)(bg_src + (size_t)(k0 + BK) * FSH);
            bgr[1] = *(const float4*)(bg_src + (size_t)(k0 + BK) * FSH + 4);
            bur[0] = *(const float4*)(bu_src + (size_t)(k0 + BK) * FSH);
            bur[1] = *(const float4*)(bu_src + (size_t)(k0 + BK) * FSH + 4);
        }

        AFrag af;
        load_afrag(af, As, wrow + q, r);
#pragma unroll
        for (int s = 0; s < 4; s++) {
            const int v = s >> 1, c0 = (s & 1) * 2;
            uint32_t a0 = af.u[0][v][c0],     a1 = af.u[1][v][c0];
            uint32_t a2 = af.u[0][v][c0 + 1], a3 = af.u[1][v][c0 + 1];
            const float* brow0g = Bgs + (size_t)(s * 8 + r) * PITCH_B;
            const float* brow1g = Bgs + (size_t)(s * 8 + 4 + r) * PITCH_B;
            const float* brow0u = Bus + (size_t)(s * 8 + r) * PITCH_B;
            const float* brow1u = Bus + (size_t)(s * 8 + 4 + r) * PITCH_B;
#pragma unroll
            for (int nt = 0; nt < 8; nt++) {
                int nc = nt * 8 + q;
                uint32_t bg0 = f2tf32(brow0g[nc]);
                uint32_t bg1 = f2tf32(brow1g[nc]);
                mma_tf32(accg[nt][0], accg[nt][1], accg[nt][2], accg[nt][3],
                         a0, a1, a2, a3, bg0, bg1);
                uint32_t bu0 = f2tf32(brow0u[nc]);
                uint32_t bu1 = f2tf32(brow1u[nc]);
                mma_tf32(accu[nt][0], accu[nt][1], accu[nt][2], accu[nt][3],
                         a0, a1, a2, a3, bu0, bu1);
            }
        }
    }

#pragma unroll
    for (int h = 0; h < 2; h++) {
        int m = rowbase + wrow + q + h * 8;
        float* dst = g_hs + (size_t)m * FSH + n0;
#pragma unroll
        for (int nt = 0; nt < 8; nt++) {
            int cb = nt * 8 + 2 * r;
            float gv0 = accg[nt][h * 2 + 0], gv1 = accg[nt][h * 2 + 1];
            float uv0 = accu[nt][h * 2 + 0], uv1 = accu[nt][h * 2 + 1];
            dst[cb]     = (gv0 / (1.f + expf(-gv0))) * uv0;
            dst[cb + 1] = (gv1 / (1.f + expf(-gv1))) * uv1;
        }
    }
}

// ---------------------------------------------------------------------------
// Shared down GEMM + final combine
// ---------------------------------------------------------------------------
__global__ __launch_bounds__(256)
void gemm_down_shared(const float* __restrict__ sh_down,
                      float* __restrict__ out)
{
    const int rowbase = blockIdx.y * BM;
    const int n0 = blockIdx.x * BN;

    __shared__ float As[BM * PITCH_A];
    __shared__ float Bs[BK * PITCH_B];

    const int t = threadIdx.x;
    const int wid = t >> 5, lane = t & 31;
    const int q = lane >> 2, r = lane & 3;
    const int wrow = wid * 16;

    const int a_row = t >> 1, a_k0 = (t & 1) * 16;
    const float* a_src = g_hs + (size_t)(rowbase + a_row) * FSH;

    const int b_row = t >> 3, b_col = (t & 7) * 8;
    const float* b_src = sh_down + (size_t)b_row * DIM + n0 + b_col;

    float acc[8][4];
#pragma unroll
    for (int nt = 0; nt < 8; nt++)
#pragma unroll
        for (int c = 0; c < 4; c++) acc[nt][c] = 0.f;

    float4 avr[4], bvr[2];
#pragma unroll
    for (int l = 0; l < 4; l++) avr[l] = *(const float4*)(a_src + a_k0 + l * 4);
    bvr[0] = *(const float4*)(b_src);
    bvr[1] = *(const float4*)(b_src + 4);

#pragma unroll 1
    for (int k0 = 0; k0 < FSH; k0 += BK) {
        __syncthreads();
        sts_A_perm(As, a_row, a_k0, avr);
        *(float4*)&Bs[b_row * PITCH_B + b_col]     = bvr[0];
        *(float4*)&Bs[b_row * PITCH_B + b_col + 4] = bvr[1];
        __syncthreads();

        if (k0 + BK < FSH) {
#pragma unroll
            for (int l = 0; l < 4; l++)
                avr[l] = *(const float4*)(a_src + k0 + BK + a_k0 + l * 4);
            bvr[0] = *(const float4*)(b_src + (size_t)(k0 + BK) * DIM);
            bvr[1] = *(const float4*)(b_src + (size_t)(k0 + BK) * DIM + 4);
        }

        AFrag af;
        load_afrag(af, As, wrow + q, r);
#pragma unroll
        for (int s = 0; s < 4; s++) {
            const int v = s >> 1, c0 = (s & 1) * 2;
            uint32_t a0 = af.u[0][v][c0],     a1 = af.u[1][v][c0];
            uint32_t a2 = af.u[0][v][c0 + 1], a3 = af.u[1][v][c0 + 1];
            const float* brow0 = Bs + (size_t)(s * 8 + r) * PITCH_B;
            const float* brow1 = Bs + (size_t)(s * 8 + 4 + r) * PITCH_B;
#pragma unroll
            for (int nt = 0; nt < 8; nt++) {
                int nc = nt * 8 + q;
                uint32_t b0 = f2tf32(brow0[nc]);
                uint32_t b1 = f2tf32(brow1[nc]);
                mma_tf32(acc[nt][0], acc[nt][1], acc[nt][2], acc[nt][3],
                         a0, a1, a2, a3, b0, b1);
            }
        }
    }

#pragma unroll
    for (int h = 0; h < 2; h++) {
        int m = rowbase + wrow + q + h * 8;
        const float* eo0 = g_eo + (size_t)(m * 2)     * DIM + n0;
        const float* eo1 = g_eo + (size_t)(m * 2 + 1) * DIM + n0;
        float* dst = out + (size_t)m * DIM + n0;
#pragma unroll
        for (int nt = 0; nt < 8; nt++) {
            int cb = nt * 8 + 2 * r;
            dst[cb]     = acc[nt][h * 2 + 0] + eo0[cb]     + eo1[cb];
            dst[cb + 1] = acc[nt][h * 2 + 1] + eo0[cb + 1] + eo1[cb + 1];
        }
    }
}

// ---------------------------------------------------------------------------
extern "C" void kernel_launch(void* const* d_in, const int* in_sizes, int n_in,
                              void* d_out, int out_size)
{
    const float* x       = (const float*)d_in[0];
    const float* gate_w  = (const float*)d_in[1];
    const float* gate_k  = (const float*)d_in[2];
    const float* up_k    = (const float*)d_in[3];
    const float* down_k  = (const float*)d_in[4];
    const float* sh_gate = (const float*)d_in[5];
    const float* sh_up   = (const float*)d_in[6];
    const float* sh_down = (const float*)d_in[7];
    float* out = (float*)d_out;

    zero_cnt_kernel<<<1, 32>>>();
    router_kernel<<<NTOK, 128>>>(x, gate_w);
    scan_kernel<<<1, 32>>>();
    fill_kernel<<<NTOK / 256, 256>>>();

    gemm_gateup_routed<<<dim3(FF / BN, NTOK / BM, NE), 256>>>(x, gate_k, up_k);
    gemm_down_routed<<<dim3(DIM / BN, NTOK / BM, NE), 256>>>(down_k);
    gemm_gateup_shared<<<dim3(FSH / BN, NTOK / BM), 256>>>(x, sh_gate, sh_up);
    gemm_down_shared<<<dim3(DIM / BN, NTOK / BM), 256>>>(sh_down, out);
}

// round 4
// speedup vs baseline: 1.5015x; 1.5015x over previous
#include <cuda_runtime.h>
#include <math.h>
#include <stdint.h>

// Problem constants
#define NTOK 2048
#define DIM  1024
#define FF   4096
#define FSH  2048
#define NE   8
#define TOPK 2
#define NSLOT (NTOK*TOPK)

// Tiling: BM=128, BN=64, BK=16, double-buffered cp.async
// 256 thr = 8 warps in 4(M) x 2(N); warp tile 32x32 = 2 mtiles x 4 ntiles m16n8k8
#define BM 128
#define BN 64
#define BK 16
#define PA 20      // A smem pitch: [m][k], banks (20m+k)%32 = 4q+r conflict-free
#define PB 72      // B smem pitch: [k][n], banks (72k+n)%32 = 8r+q conflict-free

// ---- scratch ----
__device__ float g_act[(size_t)NSLOT * FF];
__device__ float g_eo[(size_t)NSLOT * DIM];
__device__ float g_hs[(size_t)NTOK * FSH];
__device__ float g_topw[NTOK * TOPK];
__device__ int   g_topi[NTOK * TOPK];
__device__ int   g_slot_tok[NSLOT];
__device__ float g_slot_w[NSLOT];
__device__ int   g_slot_dst[NSLOT];
__device__ int   g_cnt[NE];
__device__ int   g_off[NE + 1];

// ---------------------------------------------------------------------------
__device__ __forceinline__ uint32_t f2tf32(float x) {
    uint32_t r;
    asm("cvt.rna.tf32.f32 %0, %1;" : "=r"(r) : "f"(x));
    return r;
}

__device__ __forceinline__ void mma_tf32(float& c0, float& c1, float& c2, float& c3,
                                         uint32_t a0, uint32_t a1, uint32_t a2, uint32_t a3,
                                         uint32_t b0, uint32_t b1)
{
    asm volatile(
        "mma.sync.aligned.m16n8k8.row.col.f32.tf32.tf32.f32 "
        "{%0,%1,%2,%3},{%4,%5,%6,%7},{%8,%9},{%0,%1,%2,%3};"
        : "+f"(c0), "+f"(c1), "+f"(c2), "+f"(c3)
        : "r"(a0), "r"(a1), "r"(a2), "r"(a3), "r"(b0), "r"(b1));
}

__device__ __forceinline__ void cp16(uint32_t dst_smem, const float* src) {
    asm volatile("cp.async.cg.shared.global [%0], [%1], 16;"
                 :: "r"(dst_smem), "l"(src));
}
#define CP_COMMIT() asm volatile("cp.async.commit_group;")
#define CP_WAIT1()  asm volatile("cp.async.wait_group 1;" ::: "memory")

// ---------------------------------------------------------------------------
// Router + compaction (unchanged)
// ---------------------------------------------------------------------------
__global__ void router_kernel(const float* __restrict__ x,
                              const float* __restrict__ gate_w)
{
    const int n = blockIdx.x;
    const int tid = threadIdx.x;
    __shared__ float sred[NE][128];

    float acc[NE];
#pragma unroll
    for (int e = 0; e < NE; e++) acc[e] = 0.f;

    const float* xr = x + (size_t)n * DIM;
    for (int d = tid; d < DIM; d += 128) {
        float xv = xr[d];
#pragma unroll
        for (int e = 0; e < NE; e++)
            acc[e] = fmaf(xv, gate_w[e * DIM + d], acc[e]);
    }
#pragma unroll
    for (int e = 0; e < NE; e++) sred[e][tid] = acc[e];
    __syncthreads();

    if (tid < NE) {
        float s = 0.f;
        for (int i = 0; i < 128; i++) s += sred[tid][i];
        sred[tid][0] = s;
    }
    __syncthreads();

    if (tid == 0) {
        float lg[NE];
#pragma unroll
        for (int e = 0; e < NE; e++) lg[e] = sred[e][0];
        float mx = lg[0];
#pragma unroll
        for (int e = 1; e < NE; e++) mx = fmaxf(mx, lg[e]);
        float se = 0.f, p[NE];
#pragma unroll
        for (int e = 0; e < NE; e++) { p[e] = expf(lg[e] - mx); se += p[e]; }
        float inv = 1.f / se;
#pragma unroll
        for (int e = 0; e < NE; e++) p[e] *= inv;

        int i1 = 0; float v1 = p[0];
#pragma unroll
        for (int e = 1; e < NE; e++) if (p[e] > v1) { v1 = p[e]; i1 = e; }
        int i2 = -1; float v2 = -1.f;
#pragma unroll
        for (int e = 0; e < NE; e++) if (e != i1 && p[e] > v2) { v2 = p[e]; i2 = e; }

        g_topi[n * 2 + 0] = i1;  g_topw[n * 2 + 0] = v1;
        g_topi[n * 2 + 1] = i2;  g_topw[n * 2 + 1] = v2;
        atomicAdd(&g_cnt[i1], 1);
        atomicAdd(&g_cnt[i2], 1);
    }
}

__global__ void zero_cnt_kernel()
{
    if (threadIdx.x < NE) g_cnt[threadIdx.x] = 0;
}

__global__ void scan_kernel()
{
    if (threadIdx.x == 0) {
        int r = 0;
        for (int e = 0; e < NE; e++) { g_off[e] = r; r += g_cnt[e]; g_cnt[e] = 0; }
        g_off[NE] = r;
    }
}

__global__ void fill_kernel()
{
    int n = blockIdx.x * blockDim.x + threadIdx.x;
    if (n >= NTOK) return;
#pragma unroll
    for (int k = 0; k < TOPK; k++) {
        int e = g_topi[n * 2 + k];
        int pos = atomicAdd(&g_cnt[e], 1);
        int slot = g_off[e] + pos;
        g_slot_tok[slot] = n;
        g_slot_w[slot]   = g_topw[n * 2 + k];
        g_slot_dst[slot] = n * 2 + k;
    }
}

// ---------------------------------------------------------------------------
// Routed gate+up GEMM (cp.async double-buffered) + SwiGLU + weight
// ---------------------------------------------------------------------------
__global__ __launch_bounds__(256)
void gemm_gateup_routed(const float* __restrict__ x,
                        const float* __restrict__ gate_k,
                        const float* __restrict__ up_k)
{
    const int e = blockIdx.z;
    const int cnt = g_cnt[e];
    const int rowbase = blockIdx.y * BM;
    if (rowbase >= cnt) return;
    const int off = g_off[e];
    const int n0 = blockIdx.x * BN;
    const float* __restrict__ Bg = gate_k + (size_t)e * DIM * FF;
    const float* __restrict__ Bu = up_k   + (size_t)e * DIM * FF;

    __shared__ float Am[2][BM * PA];
    __shared__ float Bgs[2][BK * PB];
    __shared__ float Bus[2][BK * PB];

    const int t = threadIdx.x;
    const int wid = t >> 5, lane = t & 31;
    const int q = lane >> 2, r = lane & 3;
    const int wm = (wid >> 1) * 32;
    const int wn = (wid & 1) * 32;

    // loaders
    const int a_row = t >> 1, a_seg = (t & 1) * 8;
    int m_g = rowbase + a_row;
    if (m_g >= cnt) m_g = cnt - 1;
    const float* a_src = x + (size_t)g_slot_tok[off + m_g] * DIM + a_seg;

    const int b_row = t >> 4, b_col = (t & 15) * 4;
    const float* bg_src = Bg + (size_t)b_row * FF + n0 + b_col;
    const float* bu_src = Bu + (size_t)b_row * FF + n0 + b_col;

    const uint32_t sAm = (uint32_t)__cvta_generic_to_shared(&Am[0][0]);
    const uint32_t sBg = (uint32_t)__cvta_generic_to_shared(&Bgs[0][0]);
    const uint32_t sBu = (uint32_t)__cvta_generic_to_shared(&Bus[0][0]);
    const uint32_t aoff = (a_row * PA + a_seg) * 4;
    const uint32_t boff = (b_row * PB + b_col) * 4;
    const uint32_t szA = BM * PA * 4, szB = BK * PB * 4;

    float accg[2][4][4], accu[2][4][4];
#pragma unroll
    for (int i = 0; i < 2; i++)
#pragma unroll
        for (int j = 0; j < 4; j++)
#pragma unroll
            for (int c = 0; c < 4; c++) { accg[i][j][c] = 0.f; accu[i][j][c] = 0.f; }

    // prologue
    cp16(sAm + aoff,      a_src);
    cp16(sAm + aoff + 16, a_src + 4);
    cp16(sBg + boff, bg_src);
    cp16(sBu + boff, bu_src);
    CP_COMMIT();

#pragma unroll 1
    for (int k0 = 0; k0 < DIM; k0 += BK) {
        const int cur = (k0 >> 4) & 1;
        if (k0 + BK < DIM) {
            const uint32_t nb = (cur ^ 1);
            cp16(sAm + nb * szA + aoff,      a_src + k0 + BK);
            cp16(sAm + nb * szA + aoff + 16, a_src + k0 + BK + 4);
            cp16(sBg + nb * szB + boff, bg_src + (size_t)(k0 + BK) * FF);
            cp16(sBu + nb * szB + boff, bu_src + (size_t)(k0 + BK) * FF);
        }
        CP_COMMIT();
        CP_WAIT1();
        __syncthreads();

        const float* A_  = Am[cur];
        const float* BG_ = Bgs[cur];
        const float* BU_ = Bus[cur];
#pragma unroll
        for (int ks = 0; ks < 2; ks++) {
            const int kb = ks * 8;
            uint32_t af[2][4];
#pragma unroll
            for (int mt = 0; mt < 2; mt++) {
                int mr = wm + mt * 16 + q;
                af[mt][0] = f2tf32(A_[mr * PA + kb + r]);
                af[mt][1] = f2tf32(A_[(mr + 8) * PA + kb + r]);
                af[mt][2] = f2tf32(A_[mr * PA + kb + 4 + r]);
                af[mt][3] = f2tf32(A_[(mr + 8) * PA + kb + 4 + r]);
            }
            uint32_t bgf[4][2], buf[4][2];
#pragma unroll
            for (int nt = 0; nt < 4; nt++) {
                int nc = wn + nt * 8 + q;
                bgf[nt][0] = f2tf32(BG_[(kb + r) * PB + nc]);
                bgf[nt][1] = f2tf32(BG_[(kb + 4 + r) * PB + nc]);
                buf[nt][0] = f2tf32(BU_[(kb + r) * PB + nc]);
                buf[nt][1] = f2tf32(BU_[(kb + 4 + r) * PB + nc]);
            }
#pragma unroll
            for (int mt = 0; mt < 2; mt++)
#pragma unroll
                for (int nt = 0; nt < 4; nt++) {
                    mma_tf32(accg[mt][nt][0], accg[mt][nt][1], accg[mt][nt][2], accg[mt][nt][3],
                             af[mt][0], af[mt][1], af[mt][2], af[mt][3], bgf[nt][0], bgf[nt][1]);
                    mma_tf32(accu[mt][nt][0], accu[mt][nt][1], accu[mt][nt][2], accu[mt][nt][3],
                             af[mt][0], af[mt][1], af[mt][2], af[mt][3], buf[nt][0], buf[nt][1]);
                }
        }
        __syncthreads();
    }

#pragma unroll
    for (int mt = 0; mt < 2; mt++) {
        int r0 = wm + mt * 16 + q;
#pragma unroll
        for (int half = 0; half < 2; half++) {
            int m = rowbase + r0 + half * 8;
            if (m < cnt) {
                int slot = off + m;
                float w = g_slot_w[slot];
                float* dst = g_act + (size_t)slot * FF + n0;
#pragma unroll
                for (int nt = 0; nt < 4; nt++) {
                    int cb = wn + nt * 8 + 2 * r;
                    float gv0 = accg[mt][nt][half * 2 + 0];
                    float gv1 = accg[mt][nt][half * 2 + 1];
                    float uv0 = accu[mt][nt][half * 2 + 0];
                    float uv1 = accu[mt][nt][half * 2 + 1];
                    dst[cb]     = w * (gv0 / (1.f + expf(-gv0))) * uv0;
                    dst[cb + 1] = w * (gv1 / (1.f + expf(-gv1))) * uv1;
                }
            }
        }
    }
}

// ---------------------------------------------------------------------------
// Routed down GEMM (cp.async double-buffered)
// ---------------------------------------------------------------------------
__global__ __launch_bounds__(256)
void gemm_down_routed(const float* __restrict__ down_k)
{
    const int e = blockIdx.z;
    const int cnt = g_cnt[e];
    const int rowbase = blockIdx.y * BM;
    if (rowbase >= cnt) return;
    const int off = g_off[e];
    const int n0 = blockIdx.x * BN;
    const float* __restrict__ B = down_k + (size_t)e * FF * DIM;

    __shared__ float Am[2][BM * PA];
    __shared__ float Bs[2][BK * PB];

    const int t = threadIdx.x;
    const int wid = t >> 5, lane = t & 31;
    const int q = lane >> 2, r = lane & 3;
    const int wm = (wid >> 1) * 32;
    const int wn = (wid & 1) * 32;

    const int a_row = t >> 1, a_seg = (t & 1) * 8;
    int m_g = rowbase + a_row;
    if (m_g >= cnt) m_g = cnt - 1;
    const float* a_src = g_act + (size_t)(off + m_g) * FF + a_seg;

    const int b_row = t >> 4, b_col = (t & 15) * 4;
    const float* b_src = B + (size_t)b_row * DIM + n0 + b_col;

    const uint32_t sAm = (uint32_t)__cvta_generic_to_shared(&Am[0][0]);
    const uint32_t sBs = (uint32_t)__cvta_generic_to_shared(&Bs[0][0]);
    const uint32_t aoff = (a_row * PA + a_seg) * 4;
    const uint32_t boff = (b_row * PB + b_col) * 4;
    const uint32_t szA = BM * PA * 4, szB = BK * PB * 4;

    float acc[2][4][4];
#pragma unroll
    for (int i = 0; i < 2; i++)
#pragma unroll
        for (int j = 0; j < 4; j++)
#pragma unroll
            for (int c = 0; c < 4; c++) acc[i][j][c] = 0.f;

    cp16(sAm + aoff,      a_src);
    cp16(sAm + aoff + 16, a_src + 4);
    cp16(sBs + boff, b_src);
    CP_COMMIT();

#pragma unroll 1
    for (int k0 = 0; k0 < FF; k0 += BK) {
        const int cur = (k0 >> 4) & 1;
        if (k0 + BK < FF) {
            const uint32_t nb = (cur ^ 1);
            cp16(sAm + nb * szA + aoff,      a_src + k0 + BK);
            cp16(sAm + nb * szA + aoff + 16, a_src + k0 + BK + 4);
            cp16(sBs + nb * szB + boff, b_src + (size_t)(k0 + BK) * DIM);
        }
        CP_COMMIT();
        CP_WAIT1();
        __syncthreads();

        const float* A_ = Am[cur];
        const float* B_ = Bs[cur];
#pragma unroll
        for (int ks = 0; ks < 2; ks++) {
            const int kb = ks * 8;
            uint32_t af[2][4];
#pragma unroll
            for (int mt = 0; mt < 2; mt++) {
                int mr = wm + mt * 16 + q;
                af[mt][0] = f2tf32(A_[mr * PA + kb + r]);
                af[mt][1] = f2tf32(A_[(mr + 8) * PA + kb + r]);
                af[mt][2] = f2tf32(A_[mr * PA + kb + 4 + r]);
                af[mt][3] = f2tf32(A_[(mr + 8) * PA + kb + 4 + r]);
            }
            uint32_t bf[4][2];
#pragma unroll
            for (int nt = 0; nt < 4; nt++) {
                int nc = wn + nt * 8 + q;
                bf[nt][0] = f2tf32(B_[(kb + r) * PB + nc]);
                bf[nt][1] = f2tf32(B_[(kb + 4 + r) * PB + nc]);
            }
#pragma unroll
            for (int mt = 0; mt < 2; mt++)
#pragma unroll
                for (int nt = 0; nt < 4; nt++)
                    mma_tf32(acc[mt][nt][0], acc[mt][nt][1], acc[mt][nt][2], acc[mt][nt][3],
                             af[mt][0], af[mt][1], af[mt][2], af[mt][3], bf[nt][0], bf[nt][1]);
        }
        __syncthreads();
    }

#pragma unroll
    for (int mt = 0; mt < 2; mt++) {
        int r0 = wm + mt * 16 + q;
#pragma unroll
        for (int half = 0; half < 2; half++) {
            int m = rowbase + r0 + half * 8;
            if (m < cnt) {
                int dst_row = g_slot_dst[off + m];
                float* dst = g_eo + (size_t)dst_row * DIM + n0;
#pragma unroll
                for (int nt = 0; nt < 4; nt++) {
                    int cb = wn + nt * 8 + 2 * r;
                    dst[cb]     = acc[mt][nt][half * 2 + 0];
                    dst[cb + 1] = acc[mt][nt][half * 2 + 1];
                }
            }
        }
    }
}

// ---------------------------------------------------------------------------
// Shared expert gate+up + SwiGLU (cp.async double-buffered)
// ---------------------------------------------------------------------------
__global__ __launch_bounds__(256)
void gemm_gateup_shared(const float* __restrict__ x,
                        const float* __restrict__ sh_gate,
                        const float* __restrict__ sh_up)
{
    const int rowbase = blockIdx.y * BM;
    const int n0 = blockIdx.x * BN;

    __shared__ float Am[2][BM * PA];
    __shared__ float Bgs[2][BK * PB];
    __shared__ float Bus[2][BK * PB];

    const int t = threadIdx.x;
    const int wid = t >> 5, lane = t & 31;
    const int q = lane >> 2, r = lane & 3;
    const int wm = (wid >> 1) * 32;
    const int wn = (wid & 1) * 32;

    const int a_row = t >> 1, a_seg = (t & 1) * 8;
    const float* a_src = x + (size_t)(rowbase + a_row) * DIM + a_seg;

    const int b_row = t >> 4, b_col = (t & 15) * 4;
    const float* bg_src = sh_gate + (size_t)b_row * FSH + n0 + b_col;
    const float* bu_src = sh_up   + (size_t)b_row * FSH + n0 + b_col;

    const uint32_t sAm = (uint32_t)__cvta_generic_to_shared(&Am[0][0]);
    const uint32_t sBg = (uint32_t)__cvta_generic_to_shared(&Bgs[0][0]);
    const uint32_t sBu = (uint32_t)__cvta_generic_to_shared(&Bus[0][0]);
    const uint32_t aoff = (a_row * PA + a_seg) * 4;
    const uint32_t boff = (b_row * PB + b_col) * 4;
    const uint32_t szA = BM * PA * 4, szB = BK * PB * 4;

    float accg[2][4][4], accu[2][4][4];
#pragma unroll
    for (int i = 0; i < 2; i++)
#pragma unroll
        for (int j = 0; j < 4; j++)
#pragma unroll
            for (int c = 0; c < 4; c++) { accg[i][j][c] = 0.f; accu[i][j][c] = 0.f; }

    cp16(sAm + aoff,      a_src);
    cp16(sAm + aoff + 16, a_src + 4);
    cp16(sBg + boff, bg_src);
    cp16(sBu + boff, bu_src);
    CP_COMMIT();

#pragma unroll 1
    for (int k0 = 0; k0 < DIM; k0 += BK) {
        const int cur = (k0 >> 4) & 1;
        if (k0 + BK < DIM) {
            const uint32_t nb = (cur ^ 1);
            cp16(sAm + nb * szA + aoff,      a_src + k0 + BK);
            cp16(sAm + nb * szA + aoff + 16, a_src + k0 + BK + 4);
            cp16(sBg + nb * szB + boff, bg_src + (size_t)(k0 + BK) * FSH);
            cp16(sBu + nb * szB + boff, bu_src + (size_t)(k0 + BK) * FSH);
        }
        CP_COMMIT();
        CP_WAIT1();
        __syncthreads();

        const float* A_  = Am[cur];
        const float* BG_ = Bgs[cur];
        const float* BU_ = Bus[cur];
#pragma unroll
        for (int ks = 0; ks < 2; ks++) {
            const int kb = ks * 8;
            uint32_t af[2][4];
#pragma unroll
            for (int mt = 0; mt < 2; mt++) {
                int mr = wm + mt * 16 + q;
                af[mt][0] = f2tf32(A_[mr * PA + kb + r]);
                af[mt][1] = f2tf32(A_[(mr + 8) * PA + kb + r]);
                af[mt][2] = f2tf32(A_[mr * PA + kb + 4 + r]);
                af[mt][3] = f2tf32(A_[(mr + 8) * PA + kb + 4 + r]);
            }
            uint32_t bgf[4][2], buf[4][2];
#pragma unroll
            for (int nt = 0; nt < 4; nt++) {
                int nc = wn + nt * 8 + q;
                bgf[nt][0] = f2tf32(BG_[(kb + r) * PB + nc]);
                bgf[nt][1] = f2tf32(BG_[(kb + 4 + r) * PB + nc]);
                buf[nt][0] = f2tf32(BU_[(kb + r) * PB + nc]);
                buf[nt][1] = f2tf32(BU_[(kb + 4 + r) * PB + nc]);
            }
#pragma unroll
            for (int mt = 0; mt < 2; mt++)
#pragma unroll
                for (int nt = 0; nt < 4; nt++) {
                    mma_tf32(accg[mt][nt][0], accg[mt][nt][1], accg[mt][nt][2], accg[mt][nt][3],
                             af[mt][0], af[mt][1], af[mt][2], af[mt][3], bgf[nt][0], bgf[nt][1]);
                    mma_tf32(accu[mt][nt][0], accu[mt][nt][1], accu[mt][nt][2], accu[mt][nt][3],
                             af[mt][0], af[mt][1], af[mt][2], af[mt][3], buf[nt][0], buf[nt][1]);
                }
        }
        __syncthreads();
    }

#pragma unroll
    for (int mt = 0; mt < 2; mt++) {
        int r0 = wm + mt * 16 + q;
#pragma unroll
        for (int half = 0; half < 2; half++) {
            int m = rowbase + r0 + half * 8;
            float* dst = g_hs + (size_t)m * FSH + n0;
#pragma unroll
            for (int nt = 0; nt < 4; nt++) {
                int cb = wn + nt * 8 + 2 * r;
                float gv0 = accg[mt][nt][half * 2 + 0];
                float gv1 = accg[mt][nt][half * 2 + 1];
                float uv0 = accu[mt][nt][half * 2 + 0];
                float uv1 = accu[mt][nt][half * 2 + 1];
                dst[cb]     = (gv0 / (1.f + expf(-gv0))) * uv0;
                dst[cb + 1] = (gv1 / (1.f + expf(-gv1))) * uv1;
            }
        }
    }
}

// ---------------------------------------------------------------------------
// Shared down GEMM + final combine (cp.async double-buffered)
// ---------------------------------------------------------------------------
__global__ __launch_bounds__(256)
void gemm_down_shared(const float* __restrict__ sh_down,
                      float* __restrict__ out)
{
    const int rowbase = blockIdx.y * BM;
    const int n0 = blockIdx.x * BN;

    __shared__ float Am[2][BM * PA];
    __shared__ float Bs[2][BK * PB];

    const int t = threadIdx.x;
    const int wid = t >> 5, lane = t & 31;
    const int q = lane >> 2, r = lane & 3;
    const int wm = (wid >> 1) * 32;
    const int wn = (wid & 1) * 32;

    const int a_row = t >> 1, a_seg = (t & 1) * 8;
    const float* a_src = g_hs + (size_t)(rowbase + a_row) * FSH + a_seg;

    const int b_row = t >> 4, b_col = (t & 15) * 4;
    const float* b_src = sh_down + (size_t)b_row * DIM + n0 + b_col;

    const uint32_t sAm = (uint32_t)__cvta_generic_to_shared(&Am[0][0]);
    const uint32_t sBs = (uint32_t)__cvta_generic_to_shared(&Bs[0][0]);
    const uint32_t aoff = (a_row * PA + a_seg) * 4;
    const uint32_t boff = (b_row * PB + b_col) * 4;
    const uint32_t szA = BM * PA * 4, szB = BK * PB * 4;

    float acc[2][4][4];
#pragma unroll
    for (int i = 0; i < 2; i++)
#pragma unroll
        for (int j = 0; j < 4; j++)
#pragma unroll
            for (int c = 0; c < 4; c++) acc[i][j][c] = 0.f;

    cp16(sAm + aoff,      a_src);
    cp16(sAm + aoff + 16, a_src + 4);
    cp16(sBs + boff, b_src);
    CP_COMMIT();

#pragma unroll 1
    for (int k0 = 0; k0 < FSH; k0 += BK) {
        const int cur = (k0 >> 4) & 1;
        if (k0 + BK < FSH) {
            const uint32_t nb = (cur ^ 1);
            cp16(sAm + nb * szA + aoff,      a_src + k0 + BK);
            cp16(sAm + nb * szA + aoff + 16, a_src + k0 + BK + 4);
            cp16(sBs + nb * szB + boff, b_src + (size_t)(k0 + BK) * DIM);
        }
        CP_COMMIT();
        CP_WAIT1();
        __syncthreads();

        const float* A_ = Am[cur];
        const float* B_ = Bs[cur];
#pragma unroll
        for (int ks = 0; ks < 2; ks++) {
            const int kb = ks * 8;
            uint32_t af[2][4];
#pragma unroll
            for (int mt = 0; mt < 2; mt++) {
                int mr = wm + mt * 16 + q;
                af[mt][0] = f2tf32(A_[mr * PA + kb + r]);
                af[mt][1] = f2tf32(A_[(mr + 8) * PA + kb + r]);
                af[mt][2] = f2tf32(A_[mr * PA + kb + 4 + r]);
                af[mt][3] = f2tf32(A_[(mr + 8) * PA + kb + 4 + r]);
            }
            uint32_t bf[4][2];
#pragma unroll
            for (int nt = 0; nt < 4; nt++) {
                int nc = wn + nt * 8 + q;
                bf[nt][0] = f2tf32(B_[(kb + r) * PB + nc]);
                bf[nt][1] = f2tf32(B_[(kb + 4 + r) * PB + nc]);
            }
#pragma unroll
            for (int mt = 0; mt < 2; mt++)
#pragma unroll
                for (int nt = 0; nt < 4; nt++)
                    mma_tf32(acc[mt][nt][0], acc[mt][nt][1], acc[mt][nt][2], acc[mt][nt][3],
                             af[mt][0], af[mt][1], af[mt][2], af[mt][3], bf[nt][0], bf[nt][1]);
        }
        __syncthreads();
    }

#pragma unroll
    for (int mt = 0; mt < 2; mt++) {
        int r0 = wm + mt * 16 + q;
#pragma unroll
        for (int half = 0; half < 2; half++) {
            int m = rowbase + r0 + half * 8;
            const float* eo0 = g_eo + (size_t)(m * 2)     * DIM + n0;
            const float* eo1 = g_eo + (size_t)(m * 2 + 1) * DIM + n0;
            float* dst = out + (size_t)m * DIM + n0;
#pragma unroll
            for (int nt = 0; nt < 4; nt++) {
                int cb = wn + nt * 8 + 2 * r;
                dst[cb]     = acc[mt][nt][half * 2 + 0] + eo0[cb]     + eo1[cb];
                dst[cb + 1] = acc[mt][nt][half * 2 + 1] + eo0[cb + 1] + eo1[cb + 1];
            }
        }
    }
}

// ---------------------------------------------------------------------------
extern "C" void kernel_launch(void* const* d_in, const int* in_sizes, int n_in,
                              void* d_out, int out_size)
{
    const float* x       = (const float*)d_in[0];
    const float* gate_w  = (const float*)d_in[1];
    const float* gate_k  = (const float*)d_in[2];
    const float* up_k    = (const float*)d_in[3];
    const float* down_k  = (const float*)d_in[4];
    const float* sh_gate = (const float*)d_in[5];
    const float* sh_up   = (const float*)d_in[6];
    const float* sh_down = (const float*)d_in[7];
    float* out = (float*)d_out;

    zero_cnt_kernel<<<1, 32>>>();
    router_kernel<<<NTOK, 128>>>(x, gate_w);
    scan_kernel<<<1, 32>>>();
    fill_kernel<<<NTOK / 256, 256>>>();

    gemm_gateup_routed<<<dim3(FF / BN, NTOK / BM, NE), 256>>>(x, gate_k, up_k);
    gemm_down_routed<<<dim3(DIM / BN, NTOK / BM, NE), 256>>>(down_k);
    gemm_gateup_shared<<<dim3(FSH / BN, NTOK / BM), 256>>>(x, sh_gate, sh_up);
    gemm_down_shared<<<dim3(DIM / BN, NTOK / BM), 256>>>(sh_down, out);
}

// round 5
// speedup vs baseline: 1.5229x; 1.0143x over previous
#include <cuda_runtime.h>
#include <math.h>
#include <stdint.h>

// Problem constants
#define NTOK 2048
#define DIM  1024
#define FF   4096
#define FSH  2048
#define NE   8
#define TOPK 2
#define NSLOT (NTOK*TOPK)

// Tiling: BM=128, BN=64, BK=16, double-buffered cp.async
// 256 thr = 8 warps in 4(M) x 2(N); warp tile 32x32 = 2 mtiles x 4 ntiles m16n8k8
#define BM 128
#define BN 64
#define BK 16
#define PA 20      // A smem pitch: [m][k], banks (20m+k)%32 = 4q+r conflict-free
#define PB 72      // B smem pitch: [k][n], banks (72k+n)%32 = 8r+q conflict-free

// ---- scratch ----
__device__ float g_act[(size_t)NSLOT * FF];
__device__ float g_eo[(size_t)NSLOT * DIM];
__device__ float g_hs[(size_t)NTOK * FSH];
__device__ float g_topw[NTOK * TOPK];
__device__ int   g_topi[NTOK * TOPK];
__device__ int   g_slot_tok[NSLOT];
__device__ float g_slot_w[NSLOT];
__device__ int   g_slot_dst[NSLOT];
__device__ int   g_cnt[NE];
__device__ int   g_off[NE + 1];

// ---------------------------------------------------------------------------
__device__ __forceinline__ uint32_t f2tf32(float x) {
    uint32_t r;
    asm("cvt.rna.tf32.f32 %0, %1;" : "=r"(r) : "f"(x));
    return r;
}

__device__ __forceinline__ void mma_tf32(float& c0, float& c1, float& c2, float& c3,
                                         uint32_t a0, uint32_t a1, uint32_t a2, uint32_t a3,
                                         uint32_t b0, uint32_t b1)
{
    asm volatile(
        "mma.sync.aligned.m16n8k8.row.col.f32.tf32.tf32.f32 "
        "{%0,%1,%2,%3},{%4,%5,%6,%7},{%8,%9},{%0,%1,%2,%3};"
        : "+f"(c0), "+f"(c1), "+f"(c2), "+f"(c3)
        : "r"(a0), "r"(a1), "r"(a2), "r"(a3), "r"(b0), "r"(b1));
}

__device__ __forceinline__ void cp16(uint32_t dst_smem, const float* src) {
    asm volatile("cp.async.cg.shared.global [%0], [%1], 16;"
                 :: "r"(dst_smem), "l"(src));
}
#define CP_COMMIT() asm volatile("cp.async.commit_group;")
#define CP_WAIT1()  asm volatile("cp.async.wait_group 1;" ::: "memory")

// ---------------------------------------------------------------------------
// Router + compaction (unchanged)
// ---------------------------------------------------------------------------
__global__ void router_kernel(const float* __restrict__ x,
                              const float* __restrict__ gate_w)
{
    const int n = blockIdx.x;
    const int tid = threadIdx.x;
    __shared__ float sred[NE][128];

    float acc[NE];
#pragma unroll
    for (int e = 0; e < NE; e++) acc[e] = 0.f;

    const float* xr = x + (size_t)n * DIM;
    for (int d = tid; d < DIM; d += 128) {
        float xv = xr[d];
#pragma unroll
        for (int e = 0; e < NE; e++)
            acc[e] = fmaf(xv, gate_w[e * DIM + d], acc[e]);
    }
#pragma unroll
    for (int e = 0; e < NE; e++) sred[e][tid] = acc[e];
    __syncthreads();

    if (tid < NE) {
        float s = 0.f;
        for (int i = 0; i < 128; i++) s += sred[tid][i];
        sred[tid][0] = s;
    }
    __syncthreads();

    if (tid == 0) {
        float lg[NE];
#pragma unroll
        for (int e = 0; e < NE; e++) lg[e] = sred[e][0];
        float mx = lg[0];
#pragma unroll
        for (int e = 1; e < NE; e++) mx = fmaxf(mx, lg[e]);
        float se = 0.f, p[NE];
#pragma unroll
        for (int e = 0; e < NE; e++) { p[e] = expf(lg[e] - mx); se += p[e]; }
        float inv = 1.f / se;
#pragma unroll
        for (int e = 0; e < NE; e++) p[e] *= inv;

        int i1 = 0; float v1 = p[0];
#pragma unroll
        for (int e = 1; e < NE; e++) if (p[e] > v1) { v1 = p[e]; i1 = e; }
        int i2 = -1; float v2 = -1.f;
#pragma unroll
        for (int e = 0; e < NE; e++) if (e != i1 && p[e] > v2) { v2 = p[e]; i2 = e; }

        g_topi[n * 2 + 0] = i1;  g_topw[n * 2 + 0] = v1;
        g_topi[n * 2 + 1] = i2;  g_topw[n * 2 + 1] = v2;
        atomicAdd(&g_cnt[i1], 1);
        atomicAdd(&g_cnt[i2], 1);
    }
}

__global__ void zero_cnt_kernel()
{
    if (threadIdx.x < NE) g_cnt[threadIdx.x] = 0;
}

__global__ void scan_kernel()
{
    if (threadIdx.x == 0) {
        int r = 0;
        for (int e = 0; e < NE; e++) { g_off[e] = r; r += g_cnt[e]; g_cnt[e] = 0; }
        g_off[NE] = r;
    }
}

__global__ void fill_kernel()
{
    int n = blockIdx.x * blockDim.x + threadIdx.x;
    if (n >= NTOK) return;
#pragma unroll
    for (int k = 0; k < TOPK; k++) {
        int e = g_topi[n * 2 + k];
        int pos = atomicAdd(&g_cnt[e], 1);
        int slot = g_off[e] + pos;
        g_slot_tok[slot] = n;
        g_slot_w[slot]   = g_topw[n * 2 + k];
        g_slot_dst[slot] = n * 2 + k;
    }
}

// ---------------------------------------------------------------------------
// Routed gate+up GEMM (cp.async double-buffered) + SwiGLU + weight
// ---------------------------------------------------------------------------
__global__ __launch_bounds__(256)
void gemm_gateup_routed(const float* __restrict__ x,
                        const float* __restrict__ gate_k,
                        const float* __restrict__ up_k)
{
    const int e = blockIdx.z;
    const int cnt = g_cnt[e];
    const int rowbase = blockIdx.y * BM;
    if (rowbase >= cnt) return;
    const int off = g_off[e];
    const int n0 = blockIdx.x * BN;
    const float* __restrict__ Bg = gate_k + (size_t)e * DIM * FF;
    const float* __restrict__ Bu = up_k   + (size_t)e * DIM * FF;

    __shared__ float Am[2][BM * PA];
    __shared__ float Bgs[2][BK * PB];
    __shared__ float Bus[2][BK * PB];

    const int t = threadIdx.x;
    const int wid = t >> 5, lane = t & 31;
    const int q = lane >> 2, r = lane & 3;
    const int wm = (wid >> 1) * 32;
    const int wn = (wid & 1) * 32;

    // loaders
    const int a_row = t >> 1, a_seg = (t & 1) * 8;
    int m_g = rowbase + a_row;
    if (m_g >= cnt) m_g = cnt - 1;
    const float* a_src = x + (size_t)g_slot_tok[off + m_g] * DIM + a_seg;

    const int b_row = t >> 4, b_col = (t & 15) * 4;
    const float* bg_src = Bg + (size_t)b_row * FF + n0 + b_col;
    const float* bu_src = Bu + (size_t)b_row * FF + n0 + b_col;

    const uint32_t sAm = (uint32_t)__cvta_generic_to_shared(&Am[0][0]);
    const uint32_t sBg = (uint32_t)__cvta_generic_to_shared(&Bgs[0][0]);
    const uint32_t sBu = (uint32_t)__cvta_generic_to_shared(&Bus[0][0]);
    const uint32_t aoff = (a_row * PA + a_seg) * 4;
    const uint32_t boff = (b_row * PB + b_col) * 4;
    const uint32_t szA = BM * PA * 4, szB = BK * PB * 4;

    float accg[2][4][4], accu[2][4][4];
#pragma unroll
    for (int i = 0; i < 2; i++)
#pragma unroll
        for (int j = 0; j < 4; j++)
#pragma unroll
            for (int c = 0; c < 4; c++) { accg[i][j][c] = 0.f; accu[i][j][c] = 0.f; }

    // prologue
    cp16(sAm + aoff,      a_src);
    cp16(sAm + aoff + 16, a_src + 4);
    cp16(sBg + boff, bg_src);
    cp16(sBu + boff, bu_src);
    CP_COMMIT();

#pragma unroll 1
    for (int k0 = 0; k0 < DIM; k0 += BK) {
        const int cur = (k0 >> 4) & 1;
        if (k0 + BK < DIM) {
            const uint32_t nb = (cur ^ 1);
            cp16(sAm + nb * szA + aoff,      a_src + k0 + BK);
            cp16(sAm + nb * szA + aoff + 16, a_src + k0 + BK + 4);
            cp16(sBg + nb * szB + boff, bg_src + (size_t)(k0 + BK) * FF);
            cp16(sBu + nb * szB + boff, bu_src + (size_t)(k0 + BK) * FF);
        }
        CP_COMMIT();
        CP_WAIT1();
        __syncthreads();

        const float* A_  = Am[cur];
        const float* BG_ = Bgs[cur];
        const float* BU_ = Bus[cur];
#pragma unroll
        for (int ks = 0; ks < 2; ks++) {
            const int kb = ks * 8;
            uint32_t af[2][4];
#pragma unroll
            for (int mt = 0; mt < 2; mt++) {
                int mr = wm + mt * 16 + q;
                af[mt][0] = f2tf32(A_[mr * PA + kb + r]);
                af[mt][1] = f2tf32(A_[(mr + 8) * PA + kb + r]);
                af[mt][2] = f2tf32(A_[mr * PA + kb + 4 + r]);
                af[mt][3] = f2tf32(A_[(mr + 8) * PA + kb + 4 + r]);
            }
            uint32_t bgf[4][2], buf[4][2];
#pragma unroll
            for (int nt = 0; nt < 4; nt++) {
                int nc = wn + nt * 8 + q;
                bgf[nt][0] = f2tf32(BG_[(kb + r) * PB + nc]);
                bgf[nt][1] = f2tf32(BG_[(kb + 4 + r) * PB + nc]);
                buf[nt][0] = f2tf32(BU_[(kb + r) * PB + nc]);
                buf[nt][1] = f2tf32(BU_[(kb + 4 + r) * PB + nc]);
            }
#pragma unroll
            for (int mt = 0; mt < 2; mt++)
#pragma unroll
                for (int nt = 0; nt < 4; nt++) {
                    mma_tf32(accg[mt][nt][0], accg[mt][nt][1], accg[mt][nt][2], accg[mt][nt][3],
                             af[mt][0], af[mt][1], af[mt][2], af[mt][3], bgf[nt][0], bgf[nt][1]);
                    mma_tf32(accu[mt][nt][0], accu[mt][nt][1], accu[mt][nt][2], accu[mt][nt][3],
                             af[mt][0], af[mt][1], af[mt][2], af[mt][3], buf[nt][0], buf[nt][1]);
                }
        }
        __syncthreads();
    }

#pragma unroll
    for (int mt = 0; mt < 2; mt++) {
        int r0 = wm + mt * 16 + q;
#pragma unroll
        for (int half = 0; half < 2; half++) {
            int m = rowbase + r0 + half * 8;
            if (m < cnt) {
                int slot = off + m;
                float w = g_slot_w[slot];
                float* dst = g_act + (size_t)slot * FF + n0;
#pragma unroll
                for (int nt = 0; nt < 4; nt++) {
                    int cb = wn + nt * 8 + 2 * r;
                    float gv0 = accg[mt][nt][half * 2 + 0];
                    float gv1 = accg[mt][nt][half * 2 + 1];
                    float uv0 = accu[mt][nt][half * 2 + 0];
                    float uv1 = accu[mt][nt][half * 2 + 1];
                    dst[cb]     = w * (gv0 / (1.f + expf(-gv0))) * uv0;
                    dst[cb + 1] = w * (gv1 / (1.f + expf(-gv1))) * uv1;
                }
            }
        }
    }
}

// ---------------------------------------------------------------------------
// Routed down GEMM (cp.async double-buffered)
// ---------------------------------------------------------------------------
__global__ __launch_bounds__(256)
void gemm_down_routed(const float* __restrict__ down_k)
{
    const int e = blockIdx.z;
    const int cnt = g_cnt[e];
    const int rowbase = blockIdx.y * BM;
    if (rowbase >= cnt) return;
    const int off = g_off[e];
    const int n0 = blockIdx.x * BN;
    const float* __restrict__ B = down_k + (size_t)e * FF * DIM;

    __shared__ float Am[2][BM * PA];
    __shared__ float Bs[2][BK * PB];

    const int t = threadIdx.x;
    const int wid = t >> 5, lane = t & 31;
    const int q = lane >> 2, r = lane & 3;
    const int wm = (wid >> 1) * 32;
    const int wn = (wid & 1) * 32;

    const int a_row = t >> 1, a_seg = (t & 1) * 8;
    int m_g = rowbase + a_row;
    if (m_g >= cnt) m_g = cnt - 1;
    const float* a_src = g_act + (size_t)(off + m_g) * FF + a_seg;

    const int b_row = t >> 4, b_col = (t & 15) * 4;
    const float* b_src = B + (size_t)b_row * DIM + n0 + b_col;

    const uint32_t sAm = (uint32_t)__cvta_generic_to_shared(&Am[0][0]);
    const uint32_t sBs = (uint32_t)__cvta_generic_to_shared(&Bs[0][0]);
    const uint32_t aoff = (a_row * PA + a_seg) * 4;
    const uint32_t boff = (b_row * PB + b_col) * 4;
    const uint32_t szA = BM * PA * 4, szB = BK * PB * 4;

    float acc[2][4][4];
#pragma unroll
    for (int i = 0; i < 2; i++)
#pragma unroll
        for (int j = 0; j < 4; j++)
#pragma unroll
            for (int c = 0; c < 4; c++) acc[i][j][c] = 0.f;

    cp16(sAm + aoff,      a_src);
    cp16(sAm + aoff + 16, a_src + 4);
    cp16(sBs + boff, b_src);
    CP_COMMIT();

#pragma unroll 1
    for (int k0 = 0; k0 < FF; k0 += BK) {
        const int cur = (k0 >> 4) & 1;
        if (k0 + BK < FF) {
            const uint32_t nb = (cur ^ 1);
            cp16(sAm + nb * szA + aoff,      a_src + k0 + BK);
            cp16(sAm + nb * szA + aoff + 16, a_src + k0 + BK + 4);
            cp16(sBs + nb * szB + boff, b_src + (size_t)(k0 + BK) * DIM);
        }
        CP_COMMIT();
        CP_WAIT1();
        __syncthreads();

        const float* A_ = Am[cur];
        const float* B_ = Bs[cur];
#pragma unroll
        for (int ks = 0; ks < 2; ks++) {
            const int kb = ks * 8;
            uint32_t af[2][4];
#pragma unroll
            for (int mt = 0; mt < 2; mt++) {
                int mr = wm + mt * 16 + q;
                af[mt][0] = f2tf32(A_[mr * PA + kb + r]);
                af[mt][1] = f2tf32(A_[(mr + 8) * PA + kb + r]);
                af[mt][2] = f2tf32(A_[mr * PA + kb + 4 + r]);
                af[mt][3] = f2tf32(A_[(mr + 8) * PA + kb + 4 + r]);
            }
            uint32_t bf[4][2];
#pragma unroll
            for (int nt = 0; nt < 4; nt++) {
                int nc = wn + nt * 8 + q;
                bf[nt][0] = f2tf32(B_[(kb + r) * PB + nc]);
                bf[nt][1] = f2tf32(B_[(kb + 4 + r) * PB + nc]);
            }
#pragma unroll
            for (int mt = 0; mt < 2; mt++)
#pragma unroll
                for (int nt = 0; nt < 4; nt++)
                    mma_tf32(acc[mt][nt][0], acc[mt][nt][1], acc[mt][nt][2], acc[mt][nt][3],
                             af[mt][0], af[mt][1], af[mt][2], af[mt][3], bf[nt][0], bf[nt][1]);
        }
        __syncthreads();
    }

#pragma unroll
    for (int mt = 0; mt < 2; mt++) {
        int r0 = wm + mt * 16 + q;
#pragma unroll
        for (int half = 0; half < 2; half++) {
            int m = rowbase + r0 + half * 8;
            if (m < cnt) {
                int dst_row = g_slot_dst[off + m];
                float* dst = g_eo + (size_t)dst_row * DIM + n0;
#pragma unroll
                for (int nt = 0; nt < 4; nt++) {
                    int cb = wn + nt * 8 + 2 * r;
                    dst[cb]     = acc[mt][nt][half * 2 + 0];
                    dst[cb + 1] = acc[mt][nt][half * 2 + 1];
                }
            }
        }
    }
}

// ---------------------------------------------------------------------------
// Shared expert gate+up + SwiGLU (cp.async double-buffered)
// ---------------------------------------------------------------------------
__global__ __launch_bounds__(256)
void gemm_gateup_shared(const float* __restrict__ x,
                        const float* __restrict__ sh_gate,
                        const float* __restrict__ sh_up)
{
    const int rowbase = blockIdx.y * BM;
    const int n0 = blockIdx.x * BN;

    __shared__ float Am[2][BM * PA];
    __shared__ float Bgs[2][BK * PB];
    __shared__ float Bus[2][BK * PB];

    const int t = threadIdx.x;
    const int wid = t >> 5, lane = t & 31;
    const int q = lane >> 2, r = lane & 3;
    const int wm = (wid >> 1) * 32;
    const int wn = (wid & 1) * 32;

    const int a_row = t >> 1, a_seg = (t & 1) * 8;
    const float* a_src = x + (size_t)(rowbase + a_row) * DIM + a_seg;

    const int b_row = t >> 4, b_col = (t & 15) * 4;
    const float* bg_src = sh_gate + (size_t)b_row * FSH + n0 + b_col;
    const float* bu_src = sh_up   + (size_t)b_row * FSH + n0 + b_col;

    const uint32_t sAm = (uint32_t)__cvta_generic_to_shared(&Am[0][0]);
    const uint32_t sBg = (uint32_t)__cvta_generic_to_shared(&Bgs[0][0]);
    const uint32_t sBu = (uint32_t)__cvta_generic_to_shared(&Bus[0][0]);
    const uint32_t aoff = (a_row * PA + a_seg) * 4;
    const uint32_t boff = (b_row * PB + b_col) * 4;
    const uint32_t szA = BM * PA * 4, szB = BK * PB * 4;

    float accg[2][4][4], accu[2][4][4];
#pragma unroll
    for (int i = 0; i < 2; i++)
#pragma unroll
        for (int j = 0; j < 4; j++)
#pragma unroll
            for (int c = 0; c < 4; c++) { accg[i][j][c] = 0.f; accu[i][j][c] = 0.f; }

    cp16(sAm + aoff,      a_src);
    cp16(sAm + aoff + 16, a_src + 4);
    cp16(sBg + boff, bg_src);
    cp16(sBu + boff, bu_src);
    CP_COMMIT();

#pragma unroll 1
    for (int k0 = 0; k0 < DIM; k0 += BK) {
        const int cur = (k0 >> 4) & 1;
        if (k0 + BK < DIM) {
            const uint32_t nb = (cur ^ 1);
            cp16(sAm + nb * szA + aoff,      a_src + k0 + BK);
            cp16(sAm + nb * szA + aoff + 16, a_src + k0 + BK + 4);
            cp16(sBg + nb * szB + boff, bg_src + (size_t)(k0 + BK) * FSH);
            cp16(sBu + nb * szB + boff, bu_src + (size_t)(k0 + BK) * FSH);
        }
        CP_COMMIT();
        CP_WAIT1();
        __syncthreads();

        const float* A_  = Am[cur];
        const float* BG_ = Bgs[cur];
        const float* BU_ = Bus[cur];
#pragma unroll
        for (int ks = 0; ks < 2; ks++) {
            const int kb = ks * 8;
            uint32_t af[2][4];
#pragma unroll
            for (int mt = 0; mt < 2; mt++) {
                int mr = wm + mt * 16 + q;
                af[mt][0] = f2tf32(A_[mr * PA + kb + r]);
                af[mt][1] = f2tf32(A_[(mr + 8) * PA + kb + r]);
                af[mt][2] = f2tf32(A_[mr * PA + kb + 4 + r]);
                af[mt][3] = f2tf32(A_[(mr + 8) * PA + kb + 4 + r]);
            }
            uint32_t bgf[4][2], buf[4][2];
#pragma unroll
            for (int nt = 0; nt < 4; nt++) {
                int nc = wn + nt * 8 + q;
                bgf[nt][0] = f2tf32(BG_[(kb + r) * PB + nc]);
                bgf[nt][1] = f2tf32(BG_[(kb + 4 + r) * PB + nc]);
                buf[nt][0] = f2tf32(BU_[(kb + r) * PB + nc]);
                buf[nt][1] = f2tf32(BU_[(kb + 4 + r) * PB + nc]);
            }
#pragma unroll
            for (int mt = 0; mt < 2; mt++)
#pragma unroll
                for (int nt = 0; nt < 4; nt++) {
                    mma_tf32(accg[mt][nt][0], accg[mt][nt][1], accg[mt][nt][2], accg[mt][nt][3],
                             af[mt][0], af[mt][1], af[mt][2], af[mt][3], bgf[nt][0], bgf[nt][1]);
                    mma_tf32(accu[mt][nt][0], accu[mt][nt][1], accu[mt][nt][2], accu[mt][nt][3],
                             af[mt][0], af[mt][1], af[mt][2], af[mt][3], buf[nt][0], buf[nt][1]);
                }
        }
        __syncthreads();
    }

#pragma unroll
    for (int mt = 0; mt < 2; mt++) {
        int r0 = wm + mt * 16 + q;
#pragma unroll
        for (int half = 0; half < 2; half++) {
            int m = rowbase + r0 + half * 8;
            float* dst = g_hs + (size_t)m * FSH + n0;
#pragma unroll
            for (int nt = 0; nt < 4; nt++) {
                int cb = wn + nt * 8 + 2 * r;
                float gv0 = accg[mt][nt][half * 2 + 0];
                float gv1 = accg[mt][nt][half * 2 + 1];
                float uv0 = accu[mt][nt][half * 2 + 0];
                float uv1 = accu[mt][nt][half * 2 + 1];
                dst[cb]     = (gv0 / (1.f + expf(-gv0))) * uv0;
                dst[cb + 1] = (gv1 / (1.f + expf(-gv1))) * uv1;
            }
        }
    }
}

// ---------------------------------------------------------------------------
// Shared down GEMM + final combine (cp.async double-buffered)
// ---------------------------------------------------------------------------
__global__ __launch_bounds__(256)
void gemm_down_shared(const float* __restrict__ sh_down,
                      float* __restrict__ out)
{
    const int rowbase = blockIdx.y * BM;
    const int n0 = blockIdx.x * BN;

    __shared__ float Am[2][BM * PA];
    __shared__ float Bs[2][BK * PB];

    const int t = threadIdx.x;
    const int wid = t >> 5, lane = t & 31;
    const int q = lane >> 2, r = lane & 3;
    const int wm = (wid >> 1) * 32;
    const int wn = (wid & 1) * 32;

    const int a_row = t >> 1, a_seg = (t & 1) * 8;
    const float* a_src = g_hs + (size_t)(rowbase + a_row) * FSH + a_seg;

    const int b_row = t >> 4, b_col = (t & 15) * 4;
    const float* b_src = sh_down + (size_t)b_row * DIM + n0 + b_col;

    const uint32_t sAm = (uint32_t)__cvta_generic_to_shared(&Am[0][0]);
    const uint32_t sBs = (uint32_t)__cvta_generic_to_shared(&Bs[0][0]);
    const uint32_t aoff = (a_row * PA + a_seg) * 4;
    const uint32_t boff = (b_row * PB + b_col) * 4;
    const uint32_t szA = BM * PA * 4, szB = BK * PB * 4;

    float acc[2][4][4];
#pragma unroll
    for (int i = 0; i < 2; i++)
#pragma unroll
        for (int j = 0; j < 4; j++)
#pragma unroll
            for (int c = 0; c < 4; c++) acc[i][j][c] = 0.f;

    cp16(sAm + aoff,      a_src);
    cp16(sAm + aoff + 16, a_src + 4);
    cp16(sBs + boff, b_src);
    CP_COMMIT();

#pragma unroll 1
    for (int k0 = 0; k0 < FSH; k0 += BK) {
        const int cur = (k0 >> 4) & 1;
        if (k0 + BK < FSH) {
            const uint32_t nb = (cur ^ 1);
            cp16(sAm + nb * szA + aoff,      a_src + k0 + BK);
            cp16(sAm + nb * szA + aoff + 16, a_src + k0 + BK + 4);
            cp16(sBs + nb * szB + boff, b_src + (size_t)(k0 + BK) * DIM);
        }
        CP_COMMIT();
        CP_WAIT1();
        __syncthreads();

        const float* A_ = Am[cur];
        const float* B_ = Bs[cur];
#pragma unroll
        for (int ks = 0; ks < 2; ks++) {
            const int kb = ks * 8;
            uint32_t af[2][4];
#pragma unroll
            for (int mt = 0; mt < 2; mt++) {
                int mr = wm + mt * 16 + q;
                af[mt][0] = f2tf32(A_[mr * PA + kb + r]);
                af[mt][1] = f2tf32(A_[(mr + 8) * PA + kb + r]);
                af[mt][2] = f2tf32(A_[mr * PA + kb + 4 + r]);
                af[mt][3] = f2tf32(A_[(mr + 8) * PA + kb + 4 + r]);
            }
            uint32_t bf[4][2];
#pragma unroll
            for (int nt = 0; nt < 4; nt++) {
                int nc = wn + nt * 8 + q;
                bf[nt][0] = f2tf32(B_[(kb + r) * PB + nc]);
                bf[nt][1] = f2tf32(B_[(kb + 4 + r) * PB + nc]);
            }
#pragma unroll
            for (int mt = 0; mt < 2; mt++)
#pragma unroll
                for (int nt = 0; nt < 4; nt++)
                    mma_tf32(acc[mt][nt][0], acc[mt][nt][1], acc[mt][nt][2], acc[mt][nt][3],
                             af[mt][0], af[mt][1], af[mt][2], af[mt][3], bf[nt][0], bf[nt][1]);
        }
        __syncthreads();
    }

#pragma unroll
    for (int mt = 0; mt < 2; mt++) {
        int r0 = wm + mt * 16 + q;
#pragma unroll
        for (int half = 0; half < 2; half++) {
            int m = rowbase + r0 + half * 8;
            const float* eo0 = g_eo + (size_t)(m * 2)     * DIM + n0;
            const float* eo1 = g_eo + (size_t)(m * 2 + 1) * DIM + n0;
            float* dst = out + (size_t)m * DIM + n0;
#pragma unroll
            for (int nt = 0; nt < 4; nt++) {
                int cb = wn + nt * 8 + 2 * r;
                dst[cb]     = acc[mt][nt][half * 2 + 0] + eo0[cb]     + eo1[cb];
                dst[cb + 1] = acc[mt][nt][half * 2 + 1] + eo0[cb + 1] + eo1[cb + 1];
            }
        }
    }
}

// ---------------------------------------------------------------------------
extern "C" void kernel_launch(void* const* d_in, const int* in_sizes, int n_in,
                              void* d_out, int out_size)
{
    const float* x       = (const float*)d_in[0];
    const float* gate_w  = (const float*)d_in[1];
    const float* gate_k  = (const float*)d_in[2];
    const float* up_k    = (const float*)d_in[3];
    const float* down_k  = (const float*)d_in[4];
    const float* sh_gate = (const float*)d_in[5];
    const float* sh_up   = (const float*)d_in[6];
    const float* sh_down = (const float*)d_in[7];
    float* out = (float*)d_out;

    zero_cnt_kernel<<<1, 32>>>();
    router_kernel<<<NTOK, 128>>>(x, gate_w);
    scan_kernel<<<1, 32>>>();
    fill_kernel<<<NTOK / 256, 256>>>();

    gemm_gateup_routed<<<dim3(FF / BN, NTOK / BM, NE), 256>>>(x, gate_k, up_k);
    gemm_down_routed<<<dim3(DIM / BN, NTOK / BM, NE), 256>>>(down_k);
    gemm_gateup_shared<<<dim3(FSH / BN, NTOK / BM), 256>>>(x, sh_gate, sh_up);
    gemm_down_shared<<<dim3(DIM / BN, NTOK / BM), 256>>>(sh_down, out);
}